// round 7
// baseline (speedup 1.0000x reference)
#include <cuda_runtime.h>
#include <cstdint>

// ---------------- config ----------------
#define GRID  444              // 3 x 148, guaranteed resident with (256,3)
#define WPB   8                // warps per block
#define TW    (GRID * WPB)     // total warps = 3552
#define NB    65536            // batch (asserted via B arg)

// ---------------- device scratch ----------------
__device__ float    g_part[GRID * 8];    // [blk][0..3]=S, [4..7]=Q
__device__ float    g_scale[8];
__device__ unsigned g_cnt  = 0;
__device__ unsigned g_flag = 0;

__device__ __forceinline__ void cp16(float4* dst_smem, const float4* src_gmem) {
    unsigned d = (unsigned)__cvta_generic_to_shared(dst_smem);
    asm volatile("cp.async.cg.shared.global [%0], [%1], 16;\n"
                 :: "r"(d), "l"(src_gmem));
}

struct cf { float re, im; };
__device__ __forceinline__ cf cmul(cf a, cf b) { return {a.re*b.re - a.im*b.im, a.re*b.im + a.im*b.re}; }
__device__ __forceinline__ cf cadd(cf a, cf b) { return {a.re + b.re, a.im + b.im}; }

__global__ __launch_bounds__(256, 3) void k_all(
    const float* __restrict__ x, const float* __restrict__ W,
    const float* __restrict__ b, const float* __restrict__ vp,
    const float* __restrict__ gamma, const float* __restrict__ beta,
    float* __restrict__ out, int B)
{
    __shared__ float4 smv[2][WPB][168];    // 43008 B: per-warp 1-sample dbl buf
    __shared__ float2 sU[256];             // sU[j*16+p] = U[p][j] * (-i)^popc(j)
    __shared__ float  sPart[WPB][8];
    __shared__ float  sScale[8];
    __shared__ unsigned sTicket;

    const int tid  = threadIdx.x;
    const int w    = tid >> 5;
    const int lane = tid & 31;
    const int hh   = lane >> 4;            // half role
    const int q    = lane & 15;            // basis index
    const int bid  = blockIdx.x;

    const unsigned epoch = *(volatile unsigned*)&g_flag;

    const float4* xv = reinterpret_cast<const float4*>(x);
    const int wg = bid * WPB + w;          // global warp id

    auto issue = [&](int s, int buf) {     // stage sample s (rows 0..23 = first 168 f4)
        const float4* src = xv + (long)s * 196;
        float4* dst = &smv[buf][w][0];
        #pragma unroll
        for (int k = 0; k < 5; k++) cp16(dst + k*32 + lane, src + k*32 + lane);
        if (lane < 8) cp16(dst + 160 + lane, src + 160 + lane);
        asm volatile("cp.async.commit_group;\n");
    };

    issue(wg, 0);                          // prologue load for everyone

    // ---- warp 0 builds (pre-rotated) U while prologue loads fly ----
    if (tid < 16) {
        const int j = tid;                 // column
        cf st[16];
        #pragma unroll
        for (int i = 0; i < 16; i++) st[i] = { (i == j) ? 1.0f : 0.0f, 0.0f };
        for (int l = 0; l < 3; l++) {
            for (int ww = 0; ww < 4; ww++) {
                float tx = vp[(l*4 + ww)*3 + 0];
                float ty = vp[(l*4 + ww)*3 + 1];
                float tz = vp[(l*4 + ww)*3 + 2];
                float cx, sx, cy, sy, cz, sz;
                sincosf(tx*0.5f, &sx, &cx);
                sincosf(ty*0.5f, &sy, &cy);
                sincosf(tz*0.5f, &sz, &cz);
                cf M00{ cy*cx,  sy*sx }, M01{ -sy*cx, -cy*sx };
                cf M10{ sy*cx, -cy*sx }, M11{  cy*cx, -sy*sx };
                cf e0{ cz, -sz }, e1{ cz, sz };
                cf G00 = cmul(e0, M00), G01 = cmul(e0, M01);
                cf G10 = cmul(e1, M10), G11 = cmul(e1, M11);
                int mask = 8 >> ww;
                #pragma unroll
                for (int i = 0; i < 16; i++) {
                    if (i & mask) continue;
                    cf a0 = st[i], a1 = st[i | mask];
                    st[i]        = cadd(cmul(G00, a0), cmul(G01, a1));
                    st[i | mask] = cadd(cmul(G10, a0), cmul(G11, a1));
                }
            }
            for (int ww = 0; ww < 3; ww++) {   // CNOT chain
                int cm = 8 >> ww, tm = 4 >> ww;
                cf tmp[16];
                #pragma unroll
                for (int i = 0; i < 16; i++) tmp[i] = st[(i & cm) ? (i ^ tm) : i];
                #pragma unroll
                for (int i = 0; i < 16; i++) st[i] = tmp[i];
            }
        }
        // bake in (-i)^popc(j) for this column
        const int pm = __popc(j) & 3;
        #pragma unroll
        for (int i = 0; i < 16; i++) {
            float r = st[i].re, im = st[i].im, nr, ni;
            if      (pm == 0) { nr =  r;  ni =  im; }
            else if (pm == 1) { nr =  im; ni = -r;  }
            else if (pm == 2) { nr = -r;  ni = -im; }
            else              { nr = -im; ni =  r;  }
            sU[j*16 + i] = make_float2(nr, ni);
        }
    }
    __syncthreads();

    // ---- per-lane constants: this half's 8 rotated-U terms for basis q ----
    float Ur[8], Ui[8];
    #pragma unroll
    for (int jj = 0; jj < 8; jj++) {
        float2 u = sU[(hh*8 + jj)*16 + q];
        Ur[jj] = u.x; Ui[jj] = u.y;
    }
    const float4 wrow = reinterpret_cast<const float4*>(W)[q];
    const float4 bv   = *reinterpret_cast<const float4*>(b);

    float runS0=0, runS1=0, runS2=0, runS3=0;
    float runQ0=0, runQ1=0, runQ2=0, runQ3=0;

    const int cb = q & 3, rb = q >> 2;
    const int poolOff = (rb*6 + hh*3)*28 + cb*6;   // this half's 3 rows

    int buf = 0;
    for (int s = wg; s < B; s += TW) {
        const int snext = s + TW;
        if (snext < B) {
            issue(snext, buf ^ 1);
            asm volatile("cp.async.wait_group 1;\n");
        } else {
            asm volatile("cp.async.wait_group 0;\n");
        }
        __syncwarp();

        // ---- pooling: half sums its 3 rows x 6 cols of bin q ----
        const float* s0f = reinterpret_cast<const float*>(&smv[buf][w][0]) + poolOff;
        float2 acc = make_float2(0.f, 0.f);
        #pragma unroll
        for (int r = 0; r < 3; r++) {
            const float2* rp = reinterpret_cast<const float2*>(s0f + r*28);
            acc.x += rp[0].x + rp[1].x + rp[2].x;
            acc.y += rp[0].y + rp[1].y + rp[2].y;
        }
        float v = acc.x + acc.y;
        v += __shfl_xor_sync(0xffffffffu, v, 16);   // combine halves
        v *= (1.0f / 36.0f);

        // ---- feats = pooled @ W + b (butterfly within 16-lane half) ----
        float f0 = v*wrow.x, f1 = v*wrow.y, f2 = v*wrow.z, f3 = v*wrow.w;
        #pragma unroll
        for (int m = 1; m < 16; m <<= 1) {
            f0 += __shfl_xor_sync(0xffffffffu, f0, m);
            f1 += __shfl_xor_sync(0xffffffffu, f1, m);
            f2 += __shfl_xor_sync(0xffffffffu, f2, m);
            f3 += __shfl_xor_sync(0xffffffffu, f3, m);
        }
        f0 += bv.x; f1 += bv.y; f2 += bv.z; f3 += bv.w;

        // ---- encoded product-state magnitudes ----
        float c0_,s_0,c1_,s_1,c2_,s_2,c3_,s_3;
        __sincosf(0.5f*f0, &s_0, &c0_);
        __sincosf(0.5f*f1, &s_1, &c1_);
        __sincosf(0.5f*f2, &s_2, &c2_);
        __sincosf(0.5f*f3, &s_3, &c3_);
        float w23[4] = { c2_*c3_, c2_*s_3, s_2*c3_, s_2*s_3 };
        // this half's two w01 values: indices hh*2, hh*2+1
        float wa = hh ? (s_0*c1_) : (c0_*c1_);
        float wb = hh ? (s_0*s_1) : (c0_*s_1);

        // ---- amp partial over this half's 8 j-terms ----
        float ar = 0.f, ai = 0.f;
        #pragma unroll
        for (int jj = 0; jj < 8; jj++) {
            float m = ((jj < 4) ? wa : wb) * w23[jj & 3];
            ar += Ur[jj]*m;
            ai += Ui[jj]*m;
        }
        ar += __shfl_xor_sync(0xffffffffu, ar, 16);
        ai += __shfl_xor_sync(0xffffffffu, ai, 16);
        float prob = ar*ar + ai*ai;

        // ---- expZ: Walsh-Hadamard butterfly over 16-lane half ----
        float v4 = prob;
        #pragma unroll
        for (int m = 1; m < 16; m <<= 1) {
            float o = __shfl_xor_sync(0xffffffffu, v4, m);
            v4 = (q & m) ? (o - v4) : (v4 + o);
        }
        float z0 = __shfl_sync(0xffffffffu, v4, 8);
        float z1 = __shfl_sync(0xffffffffu, v4, 4);
        float z2 = __shfl_sync(0xffffffffu, v4, 2);
        float z3 = __shfl_sync(0xffffffffu, v4, 1);

        if (lane == 0) {
            reinterpret_cast<float4*>(out)[s] = make_float4(z0, z1, z2, z3);
            runS0 += z0; runS1 += z1; runS2 += z2; runS3 += z3;
            runQ0 += z0*z0; runQ1 += z1*z1; runQ2 += z2*z2; runQ3 += z3*z3;
        }
        buf ^= 1;
    }

    if (lane == 0) {
        sPart[w][0] = runS0; sPart[w][1] = runS1;
        sPart[w][2] = runS2; sPart[w][3] = runS3;
        sPart[w][4] = runQ0; sPart[w][5] = runQ1;
        sPart[w][6] = runQ2; sPart[w][7] = runQ3;
    }
    __syncthreads();

    if (tid < 8) {
        float t = 0.f;
        #pragma unroll
        for (int k = 0; k < WPB; k++) t += sPart[k][tid];
        g_part[bid * 8 + tid] = t;
    }
    __threadfence();
    if (tid == 0) sTicket = atomicAdd(&g_cnt, 1u);
    __syncthreads();

    if ((sTicket % GRID) == GRID - 1) {
        __threadfence();
        float* sRed = reinterpret_cast<float*>(sU);   // 512-float scratch
        {
            int ch = tid & 7, row = tid >> 3;          // 32 rows x 8 channels
            float s = 0.f;
            for (int p2 = row; p2 < GRID; p2 += 32) s += __ldcg(&g_part[p2*8 + ch]);
            sRed[row*8 + ch] = s;
        }
        __syncthreads();
        if (tid < 8) {
            float tt = 0.f;
            #pragma unroll
            for (int r = 0; r < 32; r++) tt += sRed[r*8 + tid];
            sRed[256 + tid] = tt;
        }
        __syncthreads();
        if (tid < 4) {
            float invB = 1.0f / (float)B;
            float mu  = sRed[256 + tid] * invB;
            float var = sRed[260 + tid] * invB - mu*mu;    // biased var
            float scw = gamma[tid] * rsqrtf(var + 1e-5f);
            g_scale[tid]     = scw;
            g_scale[4 + tid] = beta[tid] - mu * scw;
        }
        __threadfence();
        __syncthreads();
        if (tid == 0) atomicAdd(&g_flag, 1u);
    }

    if (tid == 0) {
        while (*(volatile unsigned*)&g_flag == epoch) __nanosleep(64);
    }
    __syncthreads();
    __threadfence();

    if (tid < 8) sScale[tid] = *(volatile float*)&g_scale[tid];
    __syncthreads();

    // ---- normalize: one f4 per thread, coalesced ----
    {
        int i = bid * 256 + tid;
        if (i < B) {
            float4 scv = *reinterpret_cast<const float4*>(&sScale[0]);
            float4 shv = *reinterpret_cast<const float4*>(&sScale[4]);
            float4 r = reinterpret_cast<float4*>(out)[i];
            r.x = r.x*scv.x + shv.x;
            r.y = r.y*scv.y + shv.y;
            r.z = r.z*scv.z + shv.z;
            r.w = r.w*scv.w + shv.w;
            reinterpret_cast<float4*>(out)[i] = r;
        }
        // remaining samples beyond GRID*256 (none for B=65536: 444*256=113664)
        for (int i2 = GRID*256 + bid*256 + tid; i2 < B; i2 += GRID*256) {
            float4 scv = *reinterpret_cast<const float4*>(&sScale[0]);
            float4 shv = *reinterpret_cast<const float4*>(&sScale[4]);
            float4 r = reinterpret_cast<float4*>(out)[i2];
            r.x = r.x*scv.x + shv.x;
            r.y = r.y*scv.y + shv.y;
            r.z = r.z*scv.z + shv.z;
            r.w = r.w*scv.w + shv.w;
            reinterpret_cast<float4*>(out)[i2] = r;
        }
    }
}

// ---------------- launch ----------------------------------------------------
extern "C" void kernel_launch(void* const* d_in, const int* in_sizes, int n_in,
                              void* d_out, int out_size)
{
    const float* x     = (const float*)d_in[0];  // [B,1,28,28]
    const float* W     = (const float*)d_in[1];  // [16,4]
    const float* b     = (const float*)d_in[2];  // [4]
    const float* vp    = (const float*)d_in[3];  // [3,4,3]
    const float* gamma = (const float*)d_in[4];  // [4]
    const float* beta  = (const float*)d_in[5];  // [4]
    float* out = (float*)d_out;                  // [B,4]

    int B = in_sizes[0] / 784;                   // 65536

    k_all<<<GRID, 256>>>(x, W, b, vp, gamma, beta, out, B);
}